// round 3
// baseline (speedup 1.0000x reference)
#include <cuda_runtime.h>
#include <cstdint>

#define BB 2
#define CC 64
#define HH 384
#define WW 384
#define OMD 112
#define OMU 108
#define HWSZ (HH*WW)
#define NPIX (BB*HH*WW)

// Scratch (static device globals)
__device__ __align__(16) float g_value[(size_t)NPIX*CC];   // NHWC
__device__ __align__(16) float g_om[(size_t)NPIX*OMU];     // 108 f/px

extern __shared__ float dyn_smem[];

// ---------------------------------------------------------------------------
// Kernel 1: value = x @ Wv + bv  (NCHW in -> NHWC out)
// 128 px x 64 cout per block, 256 threads, 8x4 register tiles.
// smem: As[64][132] | Bs[64][68]
// ---------------------------------------------------------------------------
__global__ void __launch_bounds__(256) k_value(const float* __restrict__ inp,
                                               const float* __restrict__ Wv,
                                               const float* __restrict__ bv) {
    float* As = dyn_smem;            // 64*132
    float* Bs = As + 64 * 132;       // 64*68
    int t   = threadIdx.x;
    int px0 = blockIdx.x * 128;
    int b   = px0 / HWSZ;
    int hw0 = px0 % HWSZ;

    const float* ib = inp + (size_t)b * CC * HWSZ + hw0;
    for (int idx = t; idx < 64 * 32; idx += 256) {       // 128px/4 quads
        int c = idx >> 5, q = idx & 31;
        *reinterpret_cast<float4*>(&As[c * 132 + q * 4]) =
            *reinterpret_cast<const float4*>(ib + (size_t)c * HWSZ + q * 4);
    }
    for (int idx = t; idx < 64 * 16; idx += 256) {
        int c = idx >> 4, q = idx & 15;
        *reinterpret_cast<float4*>(&Bs[c * 68 + q * 4]) =
            *reinterpret_cast<const float4*>(Wv + c * 64 + q * 4);
    }
    __syncthreads();

    int tc = t & 15, tp = t >> 4;     // co quad, px octet
    float4 bvv = *reinterpret_cast<const float4*>(bv + tc * 4);
    float acc[8][4];
#pragma unroll
    for (int i = 0; i < 8; i++) {
        acc[i][0] = bvv.x; acc[i][1] = bvv.y; acc[i][2] = bvv.z; acc[i][3] = bvv.w;
    }
#pragma unroll
    for (int k = 0; k < 64; k++) {
        float4 a0 = *reinterpret_cast<float4*>(&As[k * 132 + tp * 8]);
        float4 a1 = *reinterpret_cast<float4*>(&As[k * 132 + tp * 8 + 4]);
        float4 w  = *reinterpret_cast<float4*>(&Bs[k * 68 + tc * 4]);
        float av[8] = {a0.x, a0.y, a0.z, a0.w, a1.x, a1.y, a1.z, a1.w};
        float wv[4] = {w.x, w.y, w.z, w.w};
#pragma unroll
        for (int i = 0; i < 8; i++)
#pragma unroll
            for (int j = 0; j < 4; j++) acc[i][j] += av[i] * wv[j];
    }

    float* vb = g_value + (size_t)px0 * 64;
#pragma unroll
    for (int i = 0; i < 8; i++) {
        float4 o = {acc[i][0], acc[i][1], acc[i][2], acc[i][3]};
        *reinterpret_cast<float4*>(vb + (tp * 8 + i) * 64 + tc * 4) = o;
    }
}

// ---------------------------------------------------------------------------
// Kernel 2 (fused): depthwise 3x3 + om GEMM (64 -> 108) + bias
// 64 px of one row per block. smem: it[64][3][66] | wom_s[64][112] |
//                                    dwt[64][68]  | bom_s[112]
// ---------------------------------------------------------------------------
__global__ void __launch_bounds__(256) k_dwom(const float* __restrict__ inp,
                                              const float* __restrict__ Wdw,
                                              const float* __restrict__ bdw,
                                              const float* __restrict__ Wom,
                                              const float* __restrict__ bom) {
    float* it    = dyn_smem;               // 64*198 = 12672
    float* wom_s = it + 64 * 198;          // 7168
    float* dwt   = wom_s + 64 * 112;       // 64*68 = 4352
    float* bom_s = dwt + 64 * 68;          // 112

    int blk  = blockIdx.x;
    int tile = blk % 6;
    int row  = (blk / 6) % HH;
    int b    = blk / (6 * HH);
    int x0   = tile * 64;
    int t    = threadIdx.x;

    for (int i = t; i < 64 * 198; i += 256) {
        int ci  = i / 198;
        int rem = i - ci * 198;
        int r   = rem / 66;
        int xx  = rem - r * 66;
        int gy = row - 1 + r;
        int gx = x0 - 1 + xx;
        float v = 0.f;
        if (gy >= 0 && gy < HH && gx >= 0 && gx < WW)
            v = inp[(size_t)(b * CC + ci) * HWSZ + (size_t)gy * WW + gx];
        it[i] = v;
    }
    for (int idx = t; idx < 1792; idx += 256) {
        int c = idx / 28, q = idx % 28;
        *reinterpret_cast<float4*>(&wom_s[c * 112 + q * 4]) =
            *reinterpret_cast<const float4*>(Wom + c * OMD + q * 4);
    }
    if (t < 112) bom_s[t] = bom[t];
    __syncthreads();

    // depthwise: channel c = t&63, 16 pixels each
    {
        int c = t & 63;
        float wd[9];
#pragma unroll
        for (int j = 0; j < 9; j++) wd[j] = Wdw[c * 9 + j];
        float bd = bdw[c];
        const float* itc = it + c * 198;
#pragma unroll
        for (int i = 0; i < 16; i++) {
            int p = (t >> 6) + i * 4;        // 0..63
            float a = bd;
#pragma unroll
            for (int r = 0; r < 3; r++)
#pragma unroll
                for (int s = 0; s < 3; s++)
                    a += itc[r * 66 + p + s] * wd[r * 3 + s];
            dwt[c * 68 + p] = a;
        }
    }
    __syncthreads();

    // GEMM: 64px x 108, 8px x 4j tiles, 216 active threads
    if (t < 216) {
        int tj = t % 27, tp = t / 27;
        float acc[8][4];
#pragma unroll
        for (int i = 0; i < 8; i++)
#pragma unroll
            for (int j = 0; j < 4; j++) acc[i][j] = bom_s[tj * 4 + j];
#pragma unroll
        for (int k = 0; k < 64; k++) {
            float4 a0 = *reinterpret_cast<float4*>(&dwt[k * 68 + tp * 8]);
            float4 a1 = *reinterpret_cast<float4*>(&dwt[k * 68 + tp * 8 + 4]);
            float4 w  = *reinterpret_cast<float4*>(&wom_s[k * 112 + tj * 4]);
            float av[8] = {a0.x, a0.y, a0.z, a0.w, a1.x, a1.y, a1.z, a1.w};
            float wv[4] = {w.x, w.y, w.z, w.w};
#pragma unroll
            for (int i = 0; i < 8; i++)
#pragma unroll
                for (int j = 0; j < 4; j++) acc[i][j] += av[i] * wv[j];
        }
        size_t pixbase = (size_t)(b * HH + row) * WW + x0;
        float* og = g_om + pixbase * OMU;
#pragma unroll
        for (int i = 0; i < 8; i++) {
            float4 o = {acc[i][0], acc[i][1], acc[i][2], acc[i][3]};
            *reinterpret_cast<float4*>(og + (tp * 8 + i) * OMU + tj * 4) = o;
        }
    }
}

// ---------------------------------------------------------------------------
// Kernel 3 (fused): deformable bilinear sampling + output GEMM (@Wo)
// 64 px of one row per block. Sampling: unit = 4 lanes (float4 of channels),
// warp = 8 units = 2px x 4 groups. Then 64x64 GEMM from smem.
// smem: om_s[64*108] | sbT[64][68] | wo_s[64][68]
// ---------------------------------------------------------------------------
__global__ void __launch_bounds__(256) k_sampout(const float* __restrict__ Wo,
                                                 float* __restrict__ out) {
    float* om_s = dyn_smem;             // 6912
    float* sbT  = om_s + 64 * 108;      // 4352  [ch][px]
    float* wo_s = sbT + 64 * 68;        // 4352  [cin][cout]

    int blk  = blockIdx.x;
    int tile = blk % 6;
    int row  = (blk / 6) % HH;
    int b    = blk / (6 * HH);
    int x0   = tile * 64;
    size_t pixbase = (size_t)(b * HH + row) * WW + x0;
    int t = threadIdx.x;

    const float4* omg = reinterpret_cast<const float4*>(g_om + pixbase * OMU);
    float4* oms4 = reinterpret_cast<float4*>(om_s);
    for (int i = t; i < 64 * 27; i += 256) oms4[i] = omg[i];
    for (int idx = t; idx < 64 * 16; idx += 256) {
        int c = idx >> 4, q = idx & 15;
        *reinterpret_cast<float4*>(&wo_s[c * 68 + q * 4]) =
            *reinterpret_cast<const float4*>(Wo + c * 64 + q * 4);
    }
    __syncthreads();

    int lane = t & 31, wrp = t >> 5;
    int u   = lane >> 2;                 // unit 0..7
    int l4  = lane & 3;
    int pxs = u & 1;                     // px within pair
    int g   = u >> 1;                    // group
    int cb  = g * 16 + l4 * 4;           // channel base (float4)
    const float* vb = g_value + (size_t)b * HWSZ * 64;
    float yf = (float)row;

    for (int it8 = 0; it8 < 4; it8++) {
        int p = it8 * 16 + wrp * 2 + pxs;      // 0..63
        float xf = (float)(x0 + p);
        const float* omp = &om_s[p * 108 + g * 27];
        float4 acc = {0.f, 0.f, 0.f, 0.f};
#pragma unroll 3
        for (int k = 0; k < 9; k++) {
            float dx = omp[2 * k];
            float dy = omp[2 * k + 1];
            float m  = omp[18 + k];
            float px = xf + (float)(k % 3 - 1) + dx;
            float py = yf + (float)(k / 3 - 1) + dy;
            float x0f = floorf(px), y0f = floorf(py);
            float wx1 = px - x0f, wy1 = py - y0f;
            int xi = (int)x0f, yi = (int)y0f;
            float wx0 = 1.f - wx1;
            float wy0 = (1.f - wy1) * m;
            wy1 *= m;
#pragma unroll
            for (int dyy = 0; dyy < 2; dyy++) {
                int yy = yi + dyy;
                float wy = dyy ? wy1 : wy0;
                bool vyd = (yy >= 0) && (yy < HH);
                int yc = min(max(yy, 0), HH - 1);
#pragma unroll
                for (int dxx = 0; dxx < 2; dxx++) {
                    int xx = xi + dxx;
                    float wx = dxx ? wx1 : wx0;
                    bool vxd = (xx >= 0) && (xx < WW);
                    int xc = min(max(xx, 0), WW - 1);
                    float wgt = (vxd && vyd) ? (wy * wx) : 0.f;
                    float4 v = *reinterpret_cast<const float4*>(
                        vb + (yc * WW + xc) * 64 + cb);
                    acc.x += wgt * v.x; acc.y += wgt * v.y;
                    acc.z += wgt * v.z; acc.w += wgt * v.w;
                }
            }
        }
        sbT[(cb + 0) * 68 + p] = acc.x;
        sbT[(cb + 1) * 68 + p] = acc.y;
        sbT[(cb + 2) * 68 + p] = acc.z;
        sbT[(cb + 3) * 68 + p] = acc.w;
    }
    __syncthreads();

    // GEMM: 64px x 64co, 4x4 tiles, all 256 threads
    int tx = t & 15, ty = t >> 4;
    float acc[4][4];
#pragma unroll
    for (int i = 0; i < 4; i++)
#pragma unroll
        for (int j = 0; j < 4; j++) acc[i][j] = 0.f;
#pragma unroll
    for (int k = 0; k < 64; k++) {
        float4 a = *reinterpret_cast<float4*>(&sbT[k * 68 + ty * 4]);
        float4 w = *reinterpret_cast<float4*>(&wo_s[k * 68 + tx * 4]);
        float av[4] = {a.x, a.y, a.z, a.w};
        float wv[4] = {w.x, w.y, w.z, w.w};
#pragma unroll
        for (int i = 0; i < 4; i++)
#pragma unroll
            for (int j = 0; j < 4; j++) acc[i][j] += av[i] * wv[j];
    }

    float* ob = out + (size_t)b * CC * HWSZ + (size_t)row * WW + x0;
#pragma unroll
    for (int j = 0; j < 4; j++) {
        int co = tx * 4 + j;
        float4 o = {acc[0][j], acc[1][j], acc[2][j], acc[3][j]};
        *reinterpret_cast<float4*>(ob + (size_t)co * HWSZ + ty * 4) = o;
    }
}

// ---------------------------------------------------------------------------
extern "C" void kernel_launch(void* const* d_in, const int* in_sizes, int n_in,
                              void* d_out, int out_size) {
    const float* inp = (const float*)d_in[0];
    const float* Wv  = (const float*)d_in[1];
    const float* bv  = (const float*)d_in[2];
    const float* Wdw = (const float*)d_in[3];
    const float* bdw = (const float*)d_in[4];
    const float* Wom = (const float*)d_in[5];
    const float* bom = (const float*)d_in[6];
    const float* Wo  = (const float*)d_in[7];
    float* out = (float*)d_out;

    const int VAL_SMEM  = (64 * 132 + 64 * 68) * 4;
    const int DWOM_SMEM = (64 * 198 + 64 * 112 + 64 * 68 + 112) * 4;
    const int SO_SMEM   = (64 * 108 + 64 * 68 + 64 * 68) * 4;
    static int smem_set = 0;
    if (!smem_set) {
        cudaFuncSetAttribute(k_value,   cudaFuncAttributeMaxDynamicSharedMemorySize, VAL_SMEM);
        cudaFuncSetAttribute(k_dwom,    cudaFuncAttributeMaxDynamicSharedMemorySize, DWOM_SMEM);
        cudaFuncSetAttribute(k_sampout, cudaFuncAttributeMaxDynamicSharedMemorySize, SO_SMEM);
        smem_set = 1;
    }

    k_value  <<<NPIX / 128,  256, VAL_SMEM>>>  (inp, Wv, bv);
    k_dwom   <<<BB * HH * 6, 256, DWOM_SMEM>>> (inp, Wdw, bdw, Wom, bom);
    k_sampout<<<BB * HH * 6, 256, SO_SMEM>>>   (Wo, out);
}

// round 4
// speedup vs baseline: 1.0444x; 1.0444x over previous
#include <cuda_runtime.h>
#include <cstdint>

#define BB 2
#define CC 64
#define HH 384
#define WW 384
#define OMD 112
#define OMU 108
#define HWSZ (HH*WW)
#define NPIX (BB*HH*WW)

typedef unsigned long long u64;

__device__ __forceinline__ u64 pack2(float lo, float hi) {
    u64 r; asm("mov.b64 %0,{%1,%2};" : "=l"(r) : "f"(lo), "f"(hi)); return r;
}
__device__ __forceinline__ u64 bcast2(float v) { return pack2(v, v); }
__device__ __forceinline__ void fma2(u64& d, u64 a, u64 b, u64 c) {
    asm("fma.rn.f32x2 %0,%1,%2,%3;" : "=l"(d) : "l"(a), "l"(b), "l"(c));
}
__device__ __forceinline__ float2 unpk(u64 v) {
    float2 r; asm("mov.b64 {%0,%1},%2;" : "=f"(r.x), "=f"(r.y) : "l"(v)); return r;
}

// Scratch
__device__ __align__(16) float g_value[(size_t)NPIX*CC];   // NHWC
__device__ __align__(16) float g_om[(size_t)NPIX*OMU];     // 108 f/px

extern __shared__ float dyn_smem[];

// ---------------------------------------------------------------------------
// Kernel 1: value = x @ Wv + bv  (NCHW in -> NHWC out)
// 128 px x 64 co per block, 256 threads, 4px x 8co tiles, f32x2 co-packed.
// ---------------------------------------------------------------------------
__global__ void __launch_bounds__(256) k_value(const float* __restrict__ inp,
                                               const float* __restrict__ Wv,
                                               const float* __restrict__ bv) {
    float* As = dyn_smem;            // 64*132
    float* Bs = As + 64 * 132;       // 64*68
    int t   = threadIdx.x;
    int px0 = blockIdx.x * 128;
    int b   = px0 / HWSZ;
    int hw0 = px0 % HWSZ;

    const float* ib = inp + (size_t)b * CC * HWSZ + hw0;
    for (int idx = t; idx < 2048; idx += 256) {
        int c = idx >> 5, q = idx & 31;
        *reinterpret_cast<float4*>(&As[c * 132 + q * 4]) =
            *reinterpret_cast<const float4*>(ib + (size_t)c * HWSZ + q * 4);
    }
    for (int idx = t; idx < 1024; idx += 256) {
        int c = idx >> 4, q = idx & 15;
        *reinterpret_cast<float4*>(&Bs[c * 68 + q * 4]) =
            *reinterpret_cast<const float4*>(Wv + c * 64 + q * 4);
    }
    __syncthreads();

    int tx = t & 7, ty = t >> 3;     // co-oct, px-quad (0..31)
    u64 acc[4][4];
#pragma unroll
    for (int jp = 0; jp < 4; jp++) {
        u64 bb = *reinterpret_cast<const u64*>(bv + tx * 8 + jp * 2);
#pragma unroll
        for (int i = 0; i < 4; i++) acc[i][jp] = bb;
    }
#pragma unroll
    for (int k = 0; k < 64; k++) {
        float4 a4 = *reinterpret_cast<float4*>(&As[k * 132 + ty * 4]);
        u64 ab[4] = {bcast2(a4.x), bcast2(a4.y), bcast2(a4.z), bcast2(a4.w)};
        const u64* wp = reinterpret_cast<const u64*>(&Bs[k * 68 + tx * 8]);
        u64 w0 = wp[0], w1 = wp[1], w2 = wp[2], w3 = wp[3];
#pragma unroll
        for (int i = 0; i < 4; i++) {
            fma2(acc[i][0], ab[i], w0, acc[i][0]);
            fma2(acc[i][1], ab[i], w1, acc[i][1]);
            fma2(acc[i][2], ab[i], w2, acc[i][2]);
            fma2(acc[i][3], ab[i], w3, acc[i][3]);
        }
    }

    float* vb = g_value + (size_t)px0 * 64;
#pragma unroll
    for (int i = 0; i < 4; i++) {
        float2 u0 = unpk(acc[i][0]), u1 = unpk(acc[i][1]);
        float2 u2 = unpk(acc[i][2]), u3 = unpk(acc[i][3]);
        float4 o0 = {u0.x, u0.y, u1.x, u1.y};
        float4 o1 = {u2.x, u2.y, u3.x, u3.y};
        float* dst = vb + (ty * 4 + i) * 64 + tx * 8;
        *reinterpret_cast<float4*>(dst)     = o0;
        *reinterpret_cast<float4*>(dst + 4) = o1;
    }
}

// ---------------------------------------------------------------------------
// Kernel 2: depthwise 3x3 + om GEMM (64 -> 108), 64 px of one row per block.
// GEMM: 8px x 4j tiles, f32x2 px-packed, 216 active threads.
// ---------------------------------------------------------------------------
__global__ void __launch_bounds__(256) k_dwom(const float* __restrict__ inp,
                                              const float* __restrict__ Wdw,
                                              const float* __restrict__ bdw,
                                              const float* __restrict__ Wom,
                                              const float* __restrict__ bom) {
    float* it    = dyn_smem;               // 64*198
    float* wom_s = it + 64 * 198;          // 64*112
    float* dwt   = wom_s + 64 * 112;       // 64*68
    float* bom_s = dwt + 64 * 68;          // 112

    int blk  = blockIdx.x;
    int tile = blk % 6;
    int row  = (blk / 6) % HH;
    int b    = blk / (6 * HH);
    int x0   = tile * 64;
    int t    = threadIdx.x;

    for (int i = t; i < 64 * 198; i += 256) {
        int ci  = i / 198;
        int rem = i - ci * 198;
        int r   = rem / 66;
        int xx  = rem - r * 66;
        int gy = row - 1 + r;
        int gx = x0 - 1 + xx;
        float v = 0.f;
        if (gy >= 0 && gy < HH && gx >= 0 && gx < WW)
            v = inp[(size_t)(b * CC + ci) * HWSZ + (size_t)gy * WW + gx];
        it[i] = v;
    }
    for (int idx = t; idx < 1792; idx += 256) {
        int c = idx / 28, q = idx % 28;
        *reinterpret_cast<float4*>(&wom_s[c * 112 + q * 4]) =
            *reinterpret_cast<const float4*>(Wom + c * OMD + q * 4);
    }
    if (t < 112) bom_s[t] = bom[t];
    __syncthreads();

    {
        int c = t & 63;
        float wd[9];
#pragma unroll
        for (int j = 0; j < 9; j++) wd[j] = Wdw[c * 9 + j];
        float bd = bdw[c];
        const float* itc = it + c * 198;
#pragma unroll
        for (int i = 0; i < 16; i++) {
            int p = (t >> 6) + i * 4;
            float a = bd;
#pragma unroll
            for (int r = 0; r < 3; r++)
#pragma unroll
                for (int s = 0; s < 3; s++)
                    a += itc[r * 66 + p + s] * wd[r * 3 + s];
            dwt[c * 68 + p] = a;
        }
    }
    __syncthreads();

    if (t < 216) {
        int tj = t % 27, tp = t / 27;      // j-quad, px-oct
        u64 acc[4][4];                      // [px-pair][j]
#pragma unroll
        for (int j = 0; j < 4; j++) {
            u64 bb = bcast2(bom_s[tj * 4 + j]);
#pragma unroll
            for (int pp = 0; pp < 4; pp++) acc[pp][j] = bb;
        }
#pragma unroll
        for (int k = 0; k < 64; k++) {
            const u64* ap = reinterpret_cast<const u64*>(&dwt[k * 68 + tp * 8]);
            u64 a0 = ap[0], a1 = ap[1], a2 = ap[2], a3 = ap[3];
            float4 w4 = *reinterpret_cast<float4*>(&wom_s[k * 112 + tj * 4]);
            u64 wb[4] = {bcast2(w4.x), bcast2(w4.y), bcast2(w4.z), bcast2(w4.w)};
#pragma unroll
            for (int j = 0; j < 4; j++) {
                fma2(acc[0][j], a0, wb[j], acc[0][j]);
                fma2(acc[1][j], a1, wb[j], acc[1][j]);
                fma2(acc[2][j], a2, wb[j], acc[2][j]);
                fma2(acc[3][j], a3, wb[j], acc[3][j]);
            }
        }
        size_t pixbase = (size_t)(b * HH + row) * WW + x0;
        float* og = g_om + pixbase * OMU;
#pragma unroll
        for (int pp = 0; pp < 4; pp++) {
            float2 u0 = unpk(acc[pp][0]), u1 = unpk(acc[pp][1]);
            float2 u2 = unpk(acc[pp][2]), u3 = unpk(acc[pp][3]);
            float4 oe = {u0.x, u1.x, u2.x, u3.x};
            float4 oo = {u0.y, u1.y, u2.y, u3.y};
            int px = tp * 8 + pp * 2;
            *reinterpret_cast<float4*>(og + px * OMU + tj * 4)       = oe;
            *reinterpret_cast<float4*>(og + (px + 1) * OMU + tj * 4) = oo;
        }
    }
}

// ---------------------------------------------------------------------------
// Kernel 3 (fused): deformable sampling (per-cell weights) + output GEMM
// 64 px of one row per block, 256 threads.
//   Phase A: thread per (px,g): scatter 9 points -> 5x5 cell weights in smem
//   Phase B: warp per px, lane = ch-pair: 25 coalesced 256B cell reads
//   Phase C: 64x64 GEMM (f32x2) -> NCHW out
// ---------------------------------------------------------------------------
__global__ void __launch_bounds__(256) k_sampout(const float* __restrict__ Wo,
                                                 float* __restrict__ out) {
    // region0: om_s (64*108) reused as sbT (64*68)
    // region1: wcell (256*26)  reused as wo_s (64*68)
    float* om_s  = dyn_smem;
    float* sbT   = dyn_smem;
    float* wcell = dyn_smem + 64 * 108;
    float* wo_s  = dyn_smem + 64 * 108;
    __shared__ int flags_s[256];

    int blk  = blockIdx.x;
    int tile = blk % 6;
    int row  = (blk / 6) % HH;
    int b    = blk / (6 * HH);
    int x0   = tile * 64;
    size_t pixbase = (size_t)(b * HH + row) * WW + x0;
    int t = threadIdx.x;

    const float4* omg = reinterpret_cast<const float4*>(g_om + pixbase * OMU);
    float4* oms4 = reinterpret_cast<float4*>(om_s);
    for (int i = t; i < 64 * 27; i += 256) oms4[i] = omg[i];
    __syncthreads();

    // ---- Phase A: per-(px,g) cell weights ----
    {
        int px = t >> 2, g = t & 3;
        const float* omp = om_s + px * 108 + g * 27;
        float* wc = wcell + t * 26;
#pragma unroll
        for (int i = 0; i < 25; i++) wc[i] = 0.f;
        int ovf = 0;
#pragma unroll
        for (int k = 0; k < 9; k++) {
            float dx = omp[2 * k];
            float dy = omp[2 * k + 1];
            float m  = omp[18 + k];
            float fx = (float)(k % 3 - 1) + dx;
            float fy = (float)(k / 3 - 1) + dy;
            float fxf = floorf(fx), fyf = floorf(fy);
            int rx = (int)fxf + 2, ry = (int)fyf + 2;
            if ((unsigned)rx <= 3u && (unsigned)ry <= 3u) {
                float wx1 = fx - fxf, wy1 = fy - fyf;
                float wx0 = 1.f - wx1;
                float wa = m * (1.f - wy1), wb = m * wy1;
                int base = ry * 5 + rx;
                wc[base]     += wa * wx0;
                wc[base + 1] += wa * wx1;
                wc[base + 5] += wb * wx0;
                wc[base + 6] += wb * wx1;
            } else ovf = 1;
        }
        flags_s[t] = ovf;
    }
    __syncthreads();

    // ---- Phase B: warp per pixel, coalesced cell gathers ----
    {
        int lane = t & 31, wrp = t >> 5;
        int c = lane * 2;
        int g = lane >> 3;
        const float* vb = g_value + (size_t)b * HWSZ * 64;
        for (int i = 0; i < 8; i++) {
            int p  = wrp * 8 + i;
            int xg = x0 + p;
            const float* wc = wcell + (p * 4 + g) * 26;
            float ax = 0.f, ay = 0.f;
#pragma unroll
            for (int ry = 0; ry < 5; ry++) {
                int yy = row + ry - 2;
                if (yy < 0 || yy >= HH) continue;
                const float* rb = vb + (size_t)yy * WW * 64;
#pragma unroll
                for (int rx = 0; rx < 5; rx++) {
                    int xx = xg + rx - 2;
                    if (xx < 0 || xx >= WW) continue;
                    float w = wc[ry * 5 + rx];
                    float2 v = *reinterpret_cast<const float2*>(rb + xx * 64 + c);
                    ax += w * v.x;
                    ay += w * v.y;
                }
            }
            // rare slow path: points outside the 5x5 window
            if (flags_s[p * 4 + g]) {
                const float* gomp = g_om + (pixbase + p) * OMU + g * 27;
                for (int k = 0; k < 9; k++) {
                    float dx = gomp[2 * k];
                    float dy = gomp[2 * k + 1];
                    float m  = gomp[18 + k];
                    float fx = (float)(k % 3 - 1) + dx;
                    float fy = (float)(k / 3 - 1) + dy;
                    float fxf = floorf(fx), fyf = floorf(fy);
                    int rx = (int)fxf + 2, ry = (int)fyf + 2;
                    if ((unsigned)rx <= 3u && (unsigned)ry <= 3u) continue;
                    float wx1 = fx - fxf, wy1 = fy - fyf;
                    int xi = xg + (int)fxf, yi = row + (int)fyf;
                    for (int dyy = 0; dyy < 2; dyy++) {
                        int yy = yi + dyy;
                        float wy = dyy ? wy1 : 1.f - wy1;
                        bool vy = (yy >= 0) && (yy < HH);
                        int yc = min(max(yy, 0), HH - 1);
                        for (int dxx = 0; dxx < 2; dxx++) {
                            int xx = xi + dxx;
                            float wx = dxx ? wx1 : 1.f - wx1;
                            bool vx = (xx >= 0) && (xx < WW);
                            int xc = min(max(xx, 0), WW - 1);
                            float wgt = (vx && vy) ? (m * wy * wx) : 0.f;
                            float2 v = *reinterpret_cast<const float2*>(
                                vb + ((size_t)yc * WW + xc) * 64 + c);
                            ax += wgt * v.x;
                            ay += wgt * v.y;
                        }
                    }
                }
            }
            sbT[c * 68 + p]       = ax;
            sbT[(c + 1) * 68 + p] = ay;
        }
    }
    __syncthreads();

    for (int idx = t; idx < 1024; idx += 256) {
        int cc = idx >> 4, q = idx & 15;
        *reinterpret_cast<float4*>(&wo_s[cc * 68 + q * 4]) =
            *reinterpret_cast<const float4*>(Wo + cc * 64 + q * 4);
    }
    __syncthreads();

    // ---- Phase C: 64px x 64co GEMM, 4px x 4co tiles, f32x2 px-packed ----
    {
        int tx = t & 15, ty = t >> 4;       // co-quad, px-quad
        u64 acc[2][4];
#pragma unroll
        for (int pp = 0; pp < 2; pp++)
#pragma unroll
            for (int j = 0; j < 4; j++) acc[pp][j] = 0ull;
#pragma unroll
        for (int k = 0; k < 64; k++) {
            const u64* ap = reinterpret_cast<const u64*>(&sbT[k * 68 + ty * 4]);
            u64 a0 = ap[0], a1 = ap[1];
            float4 w4 = *reinterpret_cast<float4*>(&wo_s[k * 68 + tx * 4]);
            u64 wb[4] = {bcast2(w4.x), bcast2(w4.y), bcast2(w4.z), bcast2(w4.w)};
#pragma unroll
            for (int j = 0; j < 4; j++) {
                fma2(acc[0][j], a0, wb[j], acc[0][j]);
                fma2(acc[1][j], a1, wb[j], acc[1][j]);
            }
        }
        float* ob = out + (size_t)b * CC * HWSZ + (size_t)row * WW + x0;
#pragma unroll
        for (int j = 0; j < 4; j++) {
            float2 u0 = unpk(acc[0][j]), u1 = unpk(acc[1][j]);
            float4 o = {u0.x, u0.y, u1.x, u1.y};
            int co = tx * 4 + j;
            *reinterpret_cast<float4*>(ob + (size_t)co * HWSZ + ty * 4) = o;
        }
    }
}

// ---------------------------------------------------------------------------
extern "C" void kernel_launch(void* const* d_in, const int* in_sizes, int n_in,
                              void* d_out, int out_size) {
    const float* inp = (const float*)d_in[0];
    const float* Wv  = (const float*)d_in[1];
    const float* bv  = (const float*)d_in[2];
    const float* Wdw = (const float*)d_in[3];
    const float* bdw = (const float*)d_in[4];
    const float* Wom = (const float*)d_in[5];
    const float* bom = (const float*)d_in[6];
    const float* Wo  = (const float*)d_in[7];
    float* out = (float*)d_out;

    const int VAL_SMEM  = (64 * 132 + 64 * 68) * 4;
    const int DWOM_SMEM = (64 * 198 + 64 * 112 + 64 * 68 + 112) * 4;
    const int SO_SMEM   = (64 * 108 + 256 * 26) * 4;
    static int smem_set = 0;
    if (!smem_set) {
        cudaFuncSetAttribute(k_value,   cudaFuncAttributeMaxDynamicSharedMemorySize, VAL_SMEM);
        cudaFuncSetAttribute(k_dwom,    cudaFuncAttributeMaxDynamicSharedMemorySize, DWOM_SMEM);
        cudaFuncSetAttribute(k_sampout, cudaFuncAttributeMaxDynamicSharedMemorySize, SO_SMEM);
        smem_set = 1;
    }

    k_value  <<<NPIX / 128,  256, VAL_SMEM>>>  (inp, Wv, bv);
    k_dwom   <<<BB * HH * 6, 256, DWOM_SMEM>>> (inp, Wdw, bdw, Wom, bom);
    k_sampout<<<BB * HH * 6, 256, SO_SMEM>>>   (Wo, out);
}

// round 5
// speedup vs baseline: 1.0737x; 1.0280x over previous
#include <cuda_runtime.h>
#include <cstdint>

#define BB 2
#define CC 64
#define HH 384
#define WW 384
#define OMD 112
#define OMU 108
#define HWSZ (HH*WW)
#define NPIX (BB*HH*WW)

typedef unsigned long long u64;

__device__ __forceinline__ u64 pack2(float lo, float hi) {
    u64 r; asm("mov.b64 %0,{%1,%2};" : "=l"(r) : "f"(lo), "f"(hi)); return r;
}
__device__ __forceinline__ u64 bcast2(float v) { return pack2(v, v); }
__device__ __forceinline__ void fma2(u64& d, u64 a, u64 b, u64 c) {
    asm("fma.rn.f32x2 %0,%1,%2,%3;" : "=l"(d) : "l"(a), "l"(b), "l"(c));
}
__device__ __forceinline__ float2 unpk(u64 v) {
    float2 r; asm("mov.b64 {%0,%1},%2;" : "=f"(r.x), "=f"(r.y) : "l"(v)); return r;
}

// Scratch
__device__ __align__(16) float g_value[(size_t)NPIX*CC];   // NHWC
__device__ __align__(16) float g_om[(size_t)NPIX*OMU];     // 108 f/px

extern __shared__ float dyn_smem[];

// ---------------------------------------------------------------------------
// Kernel 1: value = x @ Wv + bv  (NCHW in -> NHWC out)
// 256 px x 64 co per block, 256 threads, 8px x 8co tiles (co split 2 quads).
// ---------------------------------------------------------------------------
__global__ void __launch_bounds__(256) k_value(const float* __restrict__ inp,
                                               const float* __restrict__ Wv,
                                               const float* __restrict__ bv) {
    float* As = dyn_smem;            // 64*260
    float* Bs = As + 64 * 260;       // 64*68
    int t   = threadIdx.x;
    int px0 = blockIdx.x * 256;
    int b   = px0 / HWSZ;
    int hw0 = px0 % HWSZ;

    const float* ib = inp + (size_t)b * CC * HWSZ + hw0;
    for (int idx = t; idx < 4096; idx += 256) {
        int c = idx >> 6, q = idx & 63;
        *reinterpret_cast<float4*>(&As[c * 260 + q * 4]) =
            *reinterpret_cast<const float4*>(ib + (size_t)c * HWSZ + q * 4);
    }
    for (int idx = t; idx < 1024; idx += 256) {
        int c = idx >> 4, q = idx & 15;
        *reinterpret_cast<float4*>(&Bs[c * 68 + q * 4]) =
            *reinterpret_cast<const float4*>(Wv + c * 64 + q * 4);
    }
    __syncthreads();

    int tc = t & 7, tp = t >> 3;     // co-oct (split), px-oct (0..31)
    u64 acc[4][8];                    // [px-pair][co]
    {
        float4 b0 = *reinterpret_cast<const float4*>(bv + tc * 4);
        float4 b1 = *reinterpret_cast<const float4*>(bv + 32 + tc * 4);
        u64 bb[8] = {bcast2(b0.x), bcast2(b0.y), bcast2(b0.z), bcast2(b0.w),
                     bcast2(b1.x), bcast2(b1.y), bcast2(b1.z), bcast2(b1.w)};
#pragma unroll
        for (int pp = 0; pp < 4; pp++)
#pragma unroll
            for (int j = 0; j < 8; j++) acc[pp][j] = bb[j];
    }
#pragma unroll
    for (int k = 0; k < 64; k++) {
        float4 a0 = *reinterpret_cast<float4*>(&As[k * 260 + tp * 8]);
        float4 a1 = *reinterpret_cast<float4*>(&As[k * 260 + tp * 8 + 4]);
        u64 ap[4] = {pack2(a0.x, a0.y), pack2(a0.z, a0.w),
                     pack2(a1.x, a1.y), pack2(a1.z, a1.w)};
        float4 w0 = *reinterpret_cast<float4*>(&Bs[k * 68 + tc * 4]);
        float4 w1 = *reinterpret_cast<float4*>(&Bs[k * 68 + 32 + tc * 4]);
        u64 wb[8] = {bcast2(w0.x), bcast2(w0.y), bcast2(w0.z), bcast2(w0.w),
                     bcast2(w1.x), bcast2(w1.y), bcast2(w1.z), bcast2(w1.w)};
#pragma unroll
        for (int pp = 0; pp < 4; pp++)
#pragma unroll
            for (int j = 0; j < 8; j++)
                fma2(acc[pp][j], ap[pp], wb[j], acc[pp][j]);
    }

    float* vb = g_value + (size_t)px0 * 64;
#pragma unroll
    for (int pp = 0; pp < 4; pp++) {
        float2 u[8];
#pragma unroll
        for (int j = 0; j < 8; j++) u[j] = unpk(acc[pp][j]);
        int pxe = tp * 8 + pp * 2;
        float4 e0 = {u[0].x, u[1].x, u[2].x, u[3].x};
        float4 e1 = {u[4].x, u[5].x, u[6].x, u[7].x};
        float4 o0 = {u[0].y, u[1].y, u[2].y, u[3].y};
        float4 o1 = {u[4].y, u[5].y, u[6].y, u[7].y};
        float* de = vb + pxe * 64;
        *reinterpret_cast<float4*>(de + tc * 4)           = e0;
        *reinterpret_cast<float4*>(de + 32 + tc * 4)      = e1;
        *reinterpret_cast<float4*>(de + 64 + tc * 4)      = o0;
        *reinterpret_cast<float4*>(de + 96 + tc * 4)      = o1;
    }
}

// ---------------------------------------------------------------------------
// Kernel 2: depthwise 3x3 + om GEMM (64 -> 108), 64 px of one row per block.
// GEMM: warp-uniform px-octet x j-quad mapping (224 active threads).
// ---------------------------------------------------------------------------
__global__ void __launch_bounds__(256) k_dwom(const float* __restrict__ inp,
                                              const float* __restrict__ Wdw,
                                              const float* __restrict__ bdw,
                                              const float* __restrict__ Wom,
                                              const float* __restrict__ bom) {
    float* it    = dyn_smem;               // 64*198
    float* wom_s = it + 64 * 198;          // 64*112
    float* dwt   = wom_s + 64 * 112;       // 64*68
    float* bom_s = dwt + 64 * 68;          // 112

    int blk  = blockIdx.x;
    int tile = blk % 6;
    int row  = (blk / 6) % HH;
    int b    = blk / (6 * HH);
    int x0   = tile * 64;
    int t    = threadIdx.x;

    for (int i = t; i < 64 * 198; i += 256) {
        int ci  = i / 198;
        int rem = i - ci * 198;
        int r   = rem / 66;
        int xx  = rem - r * 66;
        int gy = row - 1 + r;
        int gx = x0 - 1 + xx;
        float v = 0.f;
        if (gy >= 0 && gy < HH && gx >= 0 && gx < WW)
            v = inp[(size_t)(b * CC + ci) * HWSZ + (size_t)gy * WW + gx];
        it[i] = v;
    }
    for (int idx = t; idx < 1792; idx += 256) {
        int c = idx / 28, q = idx % 28;
        *reinterpret_cast<float4*>(&wom_s[c * 112 + q * 4]) =
            *reinterpret_cast<const float4*>(Wom + c * OMD + q * 4);
    }
    if (t < 112) bom_s[t] = bom[t];
    __syncthreads();

    {
        int c = t & 63;
        float wd[9];
#pragma unroll
        for (int j = 0; j < 9; j++) wd[j] = Wdw[c * 9 + j];
        float bd = bdw[c];
        const float* itc = it + c * 198;
#pragma unroll
        for (int i = 0; i < 16; i++) {
            int p = (t >> 6) + i * 4;
            float a = bd;
#pragma unroll
            for (int r = 0; r < 3; r++)
#pragma unroll
                for (int s = 0; s < 3; s++)
                    a += itc[r * 66 + p + s] * wd[r * 3 + s];
            dwt[c * 68 + p] = a;
        }
    }
    __syncthreads();

    int jq = t & 31, tp = t >> 5;      // j-quad (<28 active), px-oct (0..7)
    if (jq < 28) {
        u64 acc[4][4];                  // [px-pair][j]
#pragma unroll
        for (int j = 0; j < 4; j++) {
            u64 bb = bcast2(bom_s[jq * 4 + j]);
#pragma unroll
            for (int pp = 0; pp < 4; pp++) acc[pp][j] = bb;
        }
#pragma unroll
        for (int k = 0; k < 64; k++) {
            float4 a0 = *reinterpret_cast<float4*>(&dwt[k * 68 + tp * 8]);
            float4 a1 = *reinterpret_cast<float4*>(&dwt[k * 68 + tp * 8 + 4]);
            u64 ap[4] = {pack2(a0.x, a0.y), pack2(a0.z, a0.w),
                         pack2(a1.x, a1.y), pack2(a1.z, a1.w)};
            float4 w4 = *reinterpret_cast<float4*>(&wom_s[k * 112 + jq * 4]);
            u64 wb[4] = {bcast2(w4.x), bcast2(w4.y), bcast2(w4.z), bcast2(w4.w)};
#pragma unroll
            for (int pp = 0; pp < 4; pp++)
#pragma unroll
                for (int j = 0; j < 4; j++)
                    fma2(acc[pp][j], ap[pp], wb[j], acc[pp][j]);
        }
        if (jq < 27) {
            size_t pixbase = (size_t)(b * HH + row) * WW + x0;
            float* og = g_om + pixbase * OMU;
#pragma unroll
            for (int pp = 0; pp < 4; pp++) {
                float2 u0 = unpk(acc[pp][0]), u1 = unpk(acc[pp][1]);
                float2 u2 = unpk(acc[pp][2]), u3 = unpk(acc[pp][3]);
                float4 oe = {u0.x, u1.x, u2.x, u3.x};
                float4 oo = {u0.y, u1.y, u2.y, u3.y};
                int px = tp * 8 + pp * 2;
                *reinterpret_cast<float4*>(og + px * OMU + jq * 4)       = oe;
                *reinterpret_cast<float4*>(og + (px + 1) * OMU + jq * 4) = oo;
            }
        }
    }
}

// ---------------------------------------------------------------------------
// Kernel 3 (fused): deformable sampling (per-cell weights) + output GEMM
// ---------------------------------------------------------------------------
template<bool CHK>
__device__ __forceinline__ void gather_cells(const float* __restrict__ vb,
                                             const float* __restrict__ wc,
                                             int row, int xg, int c,
                                             float& ax, float& ay) {
#pragma unroll
    for (int ry = 0; ry < 5; ry++) {
        int yy = row + ry - 2;
        if (CHK && (yy < 0 || yy >= HH)) continue;
        const float* rb = vb + (size_t)yy * WW * 64;
#pragma unroll
        for (int rx = 0; rx < 5; rx++) {
            int xx = xg + rx - 2;
            if (CHK && (xx < 0 || xx >= WW)) continue;
            float w = wc[ry * 5 + rx];
            float2 v = *reinterpret_cast<const float2*>(rb + xx * 64 + c);
            ax += w * v.x;
            ay += w * v.y;
        }
    }
}

__global__ void __launch_bounds__(256) k_sampout(const float* __restrict__ Wo,
                                                 float* __restrict__ out) {
    float* om_s  = dyn_smem;                 // 64*108, reused as sbT 64*68
    float* sbT   = dyn_smem;
    float* wcell = dyn_smem + 64 * 108;      // 256*26, reused as wo_s 64*68
    float* wo_s  = dyn_smem + 64 * 108;
    __shared__ int flags_s[256];

    int blk  = blockIdx.x;
    int tile = blk % 6;
    int row  = (blk / 6) % HH;
    int b    = blk / (6 * HH);
    int x0   = tile * 64;
    size_t pixbase = (size_t)(b * HH + row) * WW + x0;
    int t = threadIdx.x;
    bool interior = (row >= 2) && (row < HH - 2) && (tile >= 1) && (tile <= 4);

    const float4* omg = reinterpret_cast<const float4*>(g_om + pixbase * OMU);
    float4* oms4 = reinterpret_cast<float4*>(om_s);
    for (int i = t; i < 64 * 27; i += 256) oms4[i] = omg[i];
    __syncthreads();

    // ---- Phase A: per-(px,g) 5x5 cell weights ----
    {
        int px = t >> 2, g = t & 3;
        const float* omp = om_s + px * 108 + g * 27;
        float* wc = wcell + t * 26;
#pragma unroll
        for (int i = 0; i < 25; i++) wc[i] = 0.f;
        int ovf = 0;
#pragma unroll
        for (int k = 0; k < 9; k++) {
            float dx = omp[2 * k];
            float dy = omp[2 * k + 1];
            float m  = omp[18 + k];
            float fx = (float)(k % 3 - 1) + dx;
            float fy = (float)(k / 3 - 1) + dy;
            float fxf = floorf(fx), fyf = floorf(fy);
            int rx = (int)fxf + 2, ry = (int)fyf + 2;
            if ((unsigned)rx <= 3u && (unsigned)ry <= 3u) {
                float wx1 = fx - fxf, wy1 = fy - fyf;
                float wx0 = 1.f - wx1;
                float wa = m * (1.f - wy1), wb = m * wy1;
                int base = ry * 5 + rx;
                wc[base]     += wa * wx0;
                wc[base + 1] += wa * wx1;
                wc[base + 5] += wb * wx0;
                wc[base + 6] += wb * wx1;
            } else ovf = 1;
        }
        flags_s[t] = ovf;
    }
    __syncthreads();

    // ---- Phase B: warp per pixel, coalesced cell gathers ----
    {
        int lane = t & 31, wrp = t >> 5;
        int c = lane * 2;
        int g = lane >> 3;
        const float* vb = g_value + (size_t)b * HWSZ * 64;
        for (int i = 0; i < 8; i++) {
            int p  = wrp * 8 + i;
            int xg = x0 + p;
            const float* wc = wcell + (p * 4 + g) * 26;
            float ax = 0.f, ay = 0.f;
            if (interior) gather_cells<false>(vb, wc, row, xg, c, ax, ay);
            else          gather_cells<true >(vb, wc, row, xg, c, ax, ay);

            if (flags_s[p * 4 + g]) {      // rare: point left the 5x5 window
                const float* gomp = g_om + (pixbase + p) * OMU + g * 27;
                for (int k = 0; k < 9; k++) {
                    float dx = gomp[2 * k];
                    float dy = gomp[2 * k + 1];
                    float m  = gomp[18 + k];
                    float fx = (float)(k % 3 - 1) + dx;
                    float fy = (float)(k / 3 - 1) + dy;
                    float fxf = floorf(fx), fyf = floorf(fy);
                    int rx = (int)fxf + 2, ry = (int)fyf + 2;
                    if ((unsigned)rx <= 3u && (unsigned)ry <= 3u) continue;
                    float wx1 = fx - fxf, wy1 = fy - fyf;
                    int xi = xg + (int)fxf, yi = row + (int)fyf;
                    for (int dyy = 0; dyy < 2; dyy++) {
                        int yy = yi + dyy;
                        float wy = dyy ? wy1 : 1.f - wy1;
                        bool vy = (yy >= 0) && (yy < HH);
                        int yc = min(max(yy, 0), HH - 1);
                        for (int dxx = 0; dxx < 2; dxx++) {
                            int xx = xi + dxx;
                            float wx = dxx ? wx1 : 1.f - wx1;
                            bool vx = (xx >= 0) && (xx < WW);
                            int xc = min(max(xx, 0), WW - 1);
                            float wgt = (vx && vy) ? (m * wy * wx) : 0.f;
                            float2 v = *reinterpret_cast<const float2*>(
                                vb + ((size_t)yc * WW + xc) * 64 + c);
                            ax += wgt * v.x;
                            ay += wgt * v.y;
                        }
                    }
                }
            }
            sbT[c * 68 + p]       = ax;
            sbT[(c + 1) * 68 + p] = ay;
        }
    }
    __syncthreads();

    for (int idx = t; idx < 1024; idx += 256) {
        int cc = idx >> 4, q = idx & 15;
        *reinterpret_cast<float4*>(&wo_s[cc * 68 + q * 4]) =
            *reinterpret_cast<const float4*>(Wo + cc * 64 + q * 4);
    }
    __syncthreads();

    // ---- Phase C: 64px x 64co GEMM, 4px x 4co tiles, f32x2 px-packed ----
    {
        int tx = t & 15, ty = t >> 4;
        u64 acc[2][4];
#pragma unroll
        for (int pp = 0; pp < 2; pp++)
#pragma unroll
            for (int j = 0; j < 4; j++) acc[pp][j] = 0ull;
#pragma unroll
        for (int k = 0; k < 64; k++) {
            float4 a4 = *reinterpret_cast<float4*>(&sbT[k * 68 + ty * 4]);
            u64 a0 = pack2(a4.x, a4.y), a1 = pack2(a4.z, a4.w);
            float4 w4 = *reinterpret_cast<float4*>(&wo_s[k * 68 + tx * 4]);
            u64 wb[4] = {bcast2(w4.x), bcast2(w4.y), bcast2(w4.z), bcast2(w4.w)};
#pragma unroll
            for (int j = 0; j < 4; j++) {
                fma2(acc[0][j], a0, wb[j], acc[0][j]);
                fma2(acc[1][j], a1, wb[j], acc[1][j]);
            }
        }
        float* ob = out + (size_t)b * CC * HWSZ + (size_t)row * WW + x0;
#pragma unroll
        for (int j = 0; j < 4; j++) {
            float2 u0 = unpk(acc[0][j]), u1 = unpk(acc[1][j]);
            float4 o = {u0.x, u0.y, u1.x, u1.y};
            int co = tx * 4 + j;
            *reinterpret_cast<float4*>(ob + (size_t)co * HWSZ + ty * 4) = o;
        }
    }
}

// ---------------------------------------------------------------------------
extern "C" void kernel_launch(void* const* d_in, const int* in_sizes, int n_in,
                              void* d_out, int out_size) {
    const float* inp = (const float*)d_in[0];
    const float* Wv  = (const float*)d_in[1];
    const float* bv  = (const float*)d_in[2];
    const float* Wdw = (const float*)d_in[3];
    const float* bdw = (const float*)d_in[4];
    const float* Wom = (const float*)d_in[5];
    const float* bom = (const float*)d_in[6];
    const float* Wo  = (const float*)d_in[7];
    float* out = (float*)d_out;

    const int VAL_SMEM  = (64 * 260 + 64 * 68) * 4;
    const int DWOM_SMEM = (64 * 198 + 64 * 112 + 64 * 68 + 112) * 4;
    const int SO_SMEM   = (64 * 108 + 256 * 26) * 4;
    static int smem_set = 0;
    if (!smem_set) {
        cudaFuncSetAttribute(k_value,   cudaFuncAttributeMaxDynamicSharedMemorySize, VAL_SMEM);
        cudaFuncSetAttribute(k_dwom,    cudaFuncAttributeMaxDynamicSharedMemorySize, DWOM_SMEM);
        cudaFuncSetAttribute(k_sampout, cudaFuncAttributeMaxDynamicSharedMemorySize, SO_SMEM);
        smem_set = 1;
    }

    k_value  <<<NPIX / 256,  256, VAL_SMEM>>>  (inp, Wv, bv);
    k_dwom   <<<BB * HH * 6, 256, DWOM_SMEM>>> (inp, Wdw, bdw, Wom, bom);
    k_sampout<<<BB * HH * 6, 256, SO_SMEM>>>   (Wo, out);
}

// round 6
// speedup vs baseline: 1.2254x; 1.1413x over previous
#include <cuda_runtime.h>
#include <cstdint>

#define BB 2
#define CC 64
#define HH 384
#define WW 384
#define OMD 112
#define OMU 108
#define HWSZ (HH*WW)
#define NPIX (BB*HH*WW)

typedef unsigned long long u64;

__device__ __forceinline__ u64 pack2(float lo, float hi) {
    u64 r; asm("mov.b64 %0,{%1,%2};" : "=l"(r) : "f"(lo), "f"(hi)); return r;
}
__device__ __forceinline__ u64 bcast2(float v) { return pack2(v, v); }
__device__ __forceinline__ void fma2(u64& d, u64 a, u64 b, u64 c) {
    asm("fma.rn.f32x2 %0,%1,%2,%3;" : "=l"(d) : "l"(a), "l"(b), "l"(c));
}
__device__ __forceinline__ float2 unpk(u64 v) {
    float2 r; asm("mov.b64 {%0,%1},%2;" : "=f"(r.x), "=f"(r.y) : "l"(v)); return r;
}

// Scratch
__device__ __align__(16) float g_value[(size_t)NPIX*CC];   // NHWC
__device__ __align__(16) float g_om[(size_t)NPIX*OMU];     // 108 f/px

extern __shared__ float dyn_smem[];

// ---------------------------------------------------------------------------
// Kernel 1: value = x @ Wv + bv  (NCHW in -> NHWC out)
// 128 px x 64 co per block (51KB smem -> 4 blocks/SM), 4px x 8co tiles, f32x2.
// ---------------------------------------------------------------------------
__global__ void __launch_bounds__(256) k_value(const float* __restrict__ inp,
                                               const float* __restrict__ Wv,
                                               const float* __restrict__ bv) {
    float* As = dyn_smem;            // 64*132
    float* Bs = As + 64 * 132;       // 64*68
    int t   = threadIdx.x;
    int px0 = blockIdx.x * 128;
    int b   = px0 / HWSZ;
    int hw0 = px0 % HWSZ;

    const float* ib = inp + (size_t)b * CC * HWSZ + hw0;
    for (int idx = t; idx < 2048; idx += 256) {
        int c = idx >> 5, q = idx & 31;
        *reinterpret_cast<float4*>(&As[c * 132 + q * 4]) =
            *reinterpret_cast<const float4*>(ib + (size_t)c * HWSZ + q * 4);
    }
    for (int idx = t; idx < 1024; idx += 256) {
        int c = idx >> 4, q = idx & 15;
        *reinterpret_cast<float4*>(&Bs[c * 68 + q * 4]) =
            *reinterpret_cast<const float4*>(Wv + c * 64 + q * 4);
    }
    __syncthreads();

    int tc = t & 7, tp = t >> 3;     // co-oct (split 2 quads), px-quad (0..31)
    u64 acc[2][8];                    // [px-pair][co]
    {
        float4 b0 = *reinterpret_cast<const float4*>(bv + tc * 4);
        float4 b1 = *reinterpret_cast<const float4*>(bv + 32 + tc * 4);
        u64 bb[8] = {bcast2(b0.x), bcast2(b0.y), bcast2(b0.z), bcast2(b0.w),
                     bcast2(b1.x), bcast2(b1.y), bcast2(b1.z), bcast2(b1.w)};
#pragma unroll
        for (int pp = 0; pp < 2; pp++)
#pragma unroll
            for (int j = 0; j < 8; j++) acc[pp][j] = bb[j];
    }
#pragma unroll
    for (int k = 0; k < 64; k++) {
        float4 a4 = *reinterpret_cast<float4*>(&As[k * 132 + tp * 4]);
        u64 ap[2] = {pack2(a4.x, a4.y), pack2(a4.z, a4.w)};
        float4 w0 = *reinterpret_cast<float4*>(&Bs[k * 68 + tc * 4]);
        float4 w1 = *reinterpret_cast<float4*>(&Bs[k * 68 + 32 + tc * 4]);
        u64 wb[8] = {bcast2(w0.x), bcast2(w0.y), bcast2(w0.z), bcast2(w0.w),
                     bcast2(w1.x), bcast2(w1.y), bcast2(w1.z), bcast2(w1.w)};
#pragma unroll
        for (int pp = 0; pp < 2; pp++)
#pragma unroll
            for (int j = 0; j < 8; j++)
                fma2(acc[pp][j], ap[pp], wb[j], acc[pp][j]);
    }

    float* vb = g_value + (size_t)px0 * 64;
#pragma unroll
    for (int pp = 0; pp < 2; pp++) {
        float2 u[8];
#pragma unroll
        for (int j = 0; j < 8; j++) u[j] = unpk(acc[pp][j]);
        int pxe = tp * 4 + pp * 2;
        float4 e0 = {u[0].x, u[1].x, u[2].x, u[3].x};
        float4 e1 = {u[4].x, u[5].x, u[6].x, u[7].x};
        float4 o0 = {u[0].y, u[1].y, u[2].y, u[3].y};
        float4 o1 = {u[4].y, u[5].y, u[6].y, u[7].y};
        float* de = vb + pxe * 64;
        *reinterpret_cast<float4*>(de + tc * 4)      = e0;
        *reinterpret_cast<float4*>(de + 32 + tc * 4) = e1;
        *reinterpret_cast<float4*>(de + 64 + tc * 4) = o0;
        *reinterpret_cast<float4*>(de + 96 + tc * 4) = o1;
    }
}

// ---------------------------------------------------------------------------
// Kernel 2: depthwise 3x3 + om GEMM (64 -> 108), 64 px of one row per block.
// Conv halo streamed row-by-row through one 64x67 buffer (63.7KB total smem
// -> 3 blocks/SM). dw accumulators in registers. GEMM warp-uniform f32x2.
// ---------------------------------------------------------------------------
__global__ void __launch_bounds__(256) k_dwom(const float* __restrict__ inp,
                                              const float* __restrict__ bdw_unused_guard, // placeholder removed below
                                              const float* __restrict__ bdw,
                                              const float* __restrict__ Wom,
                                              const float* __restrict__ bom);

__global__ void __launch_bounds__(256) k_dwom2(const float* __restrict__ inp,
                                               const float* __restrict__ Wdw,
                                               const float* __restrict__ bdw,
                                               const float* __restrict__ Wom,
                                               const float* __restrict__ bom) {
    float* itr   = dyn_smem;               // 64*67  = 4288
    float* wom_s = itr + 64 * 67;          // 64*112 = 7168
    float* dwt   = wom_s + 64 * 112;       // 64*68  = 4352
    float* bom_s = dwt + 64 * 68;          // 112

    int blk  = blockIdx.x;
    int tile = blk % 6;
    int row  = (blk / 6) % HH;
    int b    = blk / (6 * HH);
    int x0   = tile * 64;
    int t    = threadIdx.x;

    for (int idx = t; idx < 1792; idx += 256) {
        int c = idx / 28, q = idx % 28;
        *reinterpret_cast<float4*>(&wom_s[c * 112 + q * 4]) =
            *reinterpret_cast<const float4*>(Wom + c * OMD + q * 4);
    }
    if (t < 112) bom_s[t] = bom[t];

    // ---- depthwise, halo streamed row by row ----
    int c  = t & 63;
    int p0 = t >> 6;                  // 0..3
    float wd[9];
#pragma unroll
    for (int j = 0; j < 9; j++) wd[j] = Wdw[c * 9 + j];
    float accv[16];
    {
        float bd = bdw[c];
#pragma unroll
        for (int i = 0; i < 16; i++) accv[i] = bd;
    }
    const float* ibs = inp + (size_t)b * CC * HWSZ;

    for (int r = 0; r < 3; r++) {
        int gy = row - 1 + r;
        __syncthreads();              // protect previous-row reads
        if (gy >= 0 && gy < HH) {
            const float* rbase = ibs + (size_t)gy * WW + x0 - 1;
            for (int i = t; i < 64 * 66; i += 256) {
                int ci = i / 66, xx = i - ci * 66;
                int gx = x0 - 1 + xx;
                float v = 0.f;
                if (gx >= 0 && gx < WW)
                    v = rbase[(size_t)ci * HWSZ + xx];
                itr[ci * 67 + xx] = v;
            }
        } else {
            for (int i = t; i < 64 * 66; i += 256) {
                int ci = i / 66, xx = i - ci * 66;
                itr[ci * 67 + xx] = 0.f;
            }
        }
        __syncthreads();
        const float* itc = itr + c * 67 + p0;
        float w0 = wd[r * 3], w1 = wd[r * 3 + 1], w2 = wd[r * 3 + 2];
#pragma unroll
        for (int i = 0; i < 16; i++) {
            const float* q = itc + i * 4;
            accv[i] += q[0] * w0 + q[1] * w1 + q[2] * w2;
        }
    }
#pragma unroll
    for (int i = 0; i < 16; i++) dwt[c * 68 + p0 + i * 4] = accv[i];
    __syncthreads();

    // ---- om GEMM: warp-uniform px-oct x j-quad, f32x2 ----
    int jq = t & 31, tp = t >> 5;
    if (jq < 27) {
        u64 acc[4][4];
#pragma unroll
        for (int j = 0; j < 4; j++) {
            u64 bb = bcast2(bom_s[jq * 4 + j]);
#pragma unroll
            for (int pp = 0; pp < 4; pp++) acc[pp][j] = bb;
        }
#pragma unroll
        for (int k = 0; k < 64; k++) {
            float4 a0 = *reinterpret_cast<float4*>(&dwt[k * 68 + tp * 8]);
            float4 a1 = *reinterpret_cast<float4*>(&dwt[k * 68 + tp * 8 + 4]);
            u64 ap[4] = {pack2(a0.x, a0.y), pack2(a0.z, a0.w),
                         pack2(a1.x, a1.y), pack2(a1.z, a1.w)};
            float4 w4 = *reinterpret_cast<float4*>(&wom_s[k * 112 + jq * 4]);
            u64 wb[4] = {bcast2(w4.x), bcast2(w4.y), bcast2(w4.z), bcast2(w4.w)};
#pragma unroll
            for (int pp = 0; pp < 4; pp++)
#pragma unroll
                for (int j = 0; j < 4; j++)
                    fma2(acc[pp][j], ap[pp], wb[j], acc[pp][j]);
        }
        size_t pixbase = (size_t)(b * HH + row) * WW + x0;
        float* og = g_om + pixbase * OMU;
#pragma unroll
        for (int pp = 0; pp < 4; pp++) {
            float2 u0 = unpk(acc[pp][0]), u1 = unpk(acc[pp][1]);
            float2 u2 = unpk(acc[pp][2]), u3 = unpk(acc[pp][3]);
            float4 oe = {u0.x, u1.x, u2.x, u3.x};
            float4 oo = {u0.y, u1.y, u2.y, u3.y};
            int px = tp * 8 + pp * 2;
            *reinterpret_cast<float4*>(og + px * OMU + jq * 4)       = oe;
            *reinterpret_cast<float4*>(og + (px + 1) * OMU + jq * 4) = oo;
        }
    }
}

// ---------------------------------------------------------------------------
// Kernel 3 (fused): deformable sampling (per-cell weights) + output GEMM
// ---------------------------------------------------------------------------
template<bool CHK>
__device__ __forceinline__ void gather_cells(const float* __restrict__ vb,
                                             const float* __restrict__ wc,
                                             int row, int xg, int c,
                                             float& ax, float& ay) {
#pragma unroll
    for (int ry = 0; ry < 5; ry++) {
        int yy = row + ry - 2;
        if (CHK && (yy < 0 || yy >= HH)) continue;
        const float* rb = vb + (size_t)yy * WW * 64;
#pragma unroll
        for (int rx = 0; rx < 5; rx++) {
            int xx = xg + rx - 2;
            if (CHK && (xx < 0 || xx >= WW)) continue;
            float w = wc[ry * 5 + rx];
            float2 v = *reinterpret_cast<const float2*>(rb + xx * 64 + c);
            ax += w * v.x;
            ay += w * v.y;
        }
    }
}

__global__ void __launch_bounds__(256) k_sampout(const float* __restrict__ Wo,
                                                 float* __restrict__ out) {
    float* om_s  = dyn_smem;                 // 64*108, reused as sbT 64*68
    float* sbT   = dyn_smem;
    float* wcell = dyn_smem + 64 * 108;      // 256*26, reused as wo_s 64*68
    float* wo_s  = dyn_smem + 64 * 108;
    __shared__ int flags_s[256];

    int blk  = blockIdx.x;
    int tile = blk % 6;
    int row  = (blk / 6) % HH;
    int b    = blk / (6 * HH);
    int x0   = tile * 64;
    size_t pixbase = (size_t)(b * HH + row) * WW + x0;
    int t = threadIdx.x;
    bool interior = (row >= 2) && (row < HH - 2) && (tile >= 1) && (tile <= 4);

    const float4* omg = reinterpret_cast<const float4*>(g_om + pixbase * OMU);
    float4* oms4 = reinterpret_cast<float4*>(om_s);
    for (int i = t; i < 64 * 27; i += 256) oms4[i] = omg[i];
    __syncthreads();

    // ---- Phase A: per-(px,g) 5x5 cell weights ----
    {
        int px = t >> 2, g = t & 3;
        const float* omp = om_s + px * 108 + g * 27;
        float* wc = wcell + t * 26;
#pragma unroll
        for (int i = 0; i < 25; i++) wc[i] = 0.f;
        int ovf = 0;
#pragma unroll
        for (int k = 0; k < 9; k++) {
            float dx = omp[2 * k];
            float dy = omp[2 * k + 1];
            float m  = omp[18 + k];
            float fx = (float)(k % 3 - 1) + dx;
            float fy = (float)(k / 3 - 1) + dy;
            float fxf = floorf(fx), fyf = floorf(fy);
            int rx = (int)fxf + 2, ry = (int)fyf + 2;
            if ((unsigned)rx <= 3u && (unsigned)ry <= 3u) {
                float wx1 = fx - fxf, wy1 = fy - fyf;
                float wx0 = 1.f - wx1;
                float wa = m * (1.f - wy1), wb = m * wy1;
                int base = ry * 5 + rx;
                wc[base]     += wa * wx0;
                wc[base + 1] += wa * wx1;
                wc[base + 5] += wb * wx0;
                wc[base + 6] += wb * wx1;
            } else ovf = 1;
        }
        flags_s[t] = ovf;
    }
    __syncthreads();

    // ---- Phase B: warp per pixel, coalesced cell gathers ----
    {
        int lane = t & 31, wrp = t >> 5;
        int c = lane * 2;
        int g = lane >> 3;
        const float* vb = g_value + (size_t)b * HWSZ * 64;
        for (int i = 0; i < 8; i++) {
            int p  = wrp * 8 + i;
            int xg = x0 + p;
            const float* wc = wcell + (p * 4 + g) * 26;
            float ax = 0.f, ay = 0.f;
            if (interior) gather_cells<false>(vb, wc, row, xg, c, ax, ay);
            else          gather_cells<true >(vb, wc, row, xg, c, ax, ay);

            if (flags_s[p * 4 + g]) {      // rare: point left the 5x5 window
                const float* gomp = g_om + (pixbase + p) * OMU + g * 27;
                for (int k = 0; k < 9; k++) {
                    float dx = gomp[2 * k];
                    float dy = gomp[2 * k + 1];
                    float m  = gomp[18 + k];
                    float fx = (float)(k % 3 - 1) + dx;
                    float fy = (float)(k / 3 - 1) + dy;
                    float fxf = floorf(fx), fyf = floorf(fy);
                    int rx = (int)fxf + 2, ry = (int)fyf + 2;
                    if ((unsigned)rx <= 3u && (unsigned)ry <= 3u) continue;
                    float wx1 = fx - fxf, wy1 = fy - fyf;
                    int xi = xg + (int)fxf, yi = row + (int)fyf;
                    for (int dyy = 0; dyy < 2; dyy++) {
                        int yy = yi + dyy;
                        float wy = dyy ? wy1 : 1.f - wy1;
                        bool vy = (yy >= 0) && (yy < HH);
                        int yc = min(max(yy, 0), HH - 1);
                        for (int dxx = 0; dxx < 2; dxx++) {
                            int xx = xi + dxx;
                            float wx = dxx ? wx1 : 1.f - wx1;
                            bool vx = (xx >= 0) && (xx < WW);
                            int xc = min(max(xx, 0), WW - 1);
                            float wgt = (vx && vy) ? (m * wy * wx) : 0.f;
                            float2 v = *reinterpret_cast<const float2*>(
                                vb + ((size_t)yc * WW + xc) * 64 + c);
                            ax += wgt * v.x;
                            ay += wgt * v.y;
                        }
                    }
                }
            }
            sbT[c * 68 + p]       = ax;
            sbT[(c + 1) * 68 + p] = ay;
        }
    }
    __syncthreads();

    for (int idx = t; idx < 1024; idx += 256) {
        int cc = idx >> 4, q = idx & 15;
        *reinterpret_cast<float4*>(&wo_s[cc * 68 + q * 4]) =
            *reinterpret_cast<const float4*>(Wo + cc * 64 + q * 4);
    }
    __syncthreads();

    // ---- Phase C: 64px x 64co GEMM, 4px x 4co tiles, f32x2 px-packed ----
    {
        int tx = t & 15, ty = t >> 4;
        u64 acc[2][4];
#pragma unroll
        for (int pp = 0; pp < 2; pp++)
#pragma unroll
            for (int j = 0; j < 4; j++) acc[pp][j] = 0ull;
#pragma unroll
        for (int k = 0; k < 64; k++) {
            float4 a4 = *reinterpret_cast<float4*>(&sbT[k * 68 + ty * 4]);
            u64 a0 = pack2(a4.x, a4.y), a1 = pack2(a4.z, a4.w);
            float4 w4 = *reinterpret_cast<float4*>(&wo_s[k * 68 + tx * 4]);
            u64 wb[4] = {bcast2(w4.x), bcast2(w4.y), bcast2(w4.z), bcast2(w4.w)};
#pragma unroll
            for (int j = 0; j < 4; j++) {
                fma2(acc[0][j], a0, wb[j], acc[0][j]);
                fma2(acc[1][j], a1, wb[j], acc[1][j]);
            }
        }
        float* ob = out + (size_t)b * CC * HWSZ + (size_t)row * WW + x0;
#pragma unroll
        for (int j = 0; j < 4; j++) {
            float2 u0 = unpk(acc[0][j]), u1 = unpk(acc[1][j]);
            float4 o = {u0.x, u0.y, u1.x, u1.y};
            int co = tx * 4 + j;
            *reinterpret_cast<float4*>(ob + (size_t)co * HWSZ + ty * 4) = o;
        }
    }
}

// ---------------------------------------------------------------------------
extern "C" void kernel_launch(void* const* d_in, const int* in_sizes, int n_in,
                              void* d_out, int out_size) {
    const float* inp = (const float*)d_in[0];
    const float* Wv  = (const float*)d_in[1];
    const float* bv  = (const float*)d_in[2];
    const float* Wdw = (const float*)d_in[3];
    const float* bdw = (const float*)d_in[4];
    const float* Wom = (const float*)d_in[5];
    const float* bom = (const float*)d_in[6];
    const float* Wo  = (const float*)d_in[7];
    float* out = (float*)d_out;

    const int VAL_SMEM  = (64 * 132 + 64 * 68) * 4;
    const int DWOM_SMEM = (64 * 67 + 64 * 112 + 64 * 68 + 112) * 4;
    const int SO_SMEM   = (64 * 108 + 256 * 26) * 4;
    static int smem_set = 0;
    if (!smem_set) {
        cudaFuncSetAttribute(k_value,   cudaFuncAttributeMaxDynamicSharedMemorySize, VAL_SMEM);
        cudaFuncSetAttribute(k_dwom2,   cudaFuncAttributeMaxDynamicSharedMemorySize, DWOM_SMEM);
        cudaFuncSetAttribute(k_sampout, cudaFuncAttributeMaxDynamicSharedMemorySize, SO_SMEM);
        smem_set = 1;
    }

    k_value  <<<NPIX / 128,  256, VAL_SMEM>>>  (inp, Wv, bv);
    k_dwom2  <<<BB * HH * 6, 256, DWOM_SMEM>>> (inp, Wdw, bdw, Wom, bom);
    k_sampout<<<BB * HH * 6, 256, SO_SMEM>>>   (Wo, out);
}

// round 7
// speedup vs baseline: 1.3612x; 1.1108x over previous
#include <cuda_runtime.h>
#include <cstdint>

#define BB 2
#define CC 64
#define HH 384
#define WW 384
#define OMD 112
#define OMU 108
#define HWSZ (HH*WW)
#define NPIX (BB*HH*WW)

typedef unsigned long long u64;

__device__ __forceinline__ u64 pack2(float lo, float hi) {
    u64 r; asm("mov.b64 %0,{%1,%2};" : "=l"(r) : "f"(lo), "f"(hi)); return r;
}
__device__ __forceinline__ u64 bcast2(float v) { return pack2(v, v); }
__device__ __forceinline__ void fma2(u64& d, u64 a, u64 b, u64 c) {
    asm("fma.rn.f32x2 %0,%1,%2,%3;" : "=l"(d) : "l"(a), "l"(b), "l"(c));
}
__device__ __forceinline__ float2 unpk(u64 v) {
    float2 r; asm("mov.b64 {%0,%1},%2;" : "=f"(r.x), "=f"(r.y) : "l"(v)); return r;
}

// Scratch
__device__ __align__(16) float g_value[(size_t)NPIX*CC];   // NHWC

extern __shared__ float dyn_smem[];

// ---------------------------------------------------------------------------
// Kernel 1: value = x @ Wv + bv  (NCHW in -> NHWC out)
// 128 px x 64 co per block, 4px x 8co tiles, f32x2.
// ---------------------------------------------------------------------------
__global__ void __launch_bounds__(256) k_value(const float* __restrict__ inp,
                                               const float* __restrict__ Wv,
                                               const float* __restrict__ bv) {
    float* As = dyn_smem;            // 64*132
    float* Bs = As + 64 * 132;       // 64*68
    int t   = threadIdx.x;
    int px0 = blockIdx.x * 128;
    int b   = px0 / HWSZ;
    int hw0 = px0 % HWSZ;

    const float* ib = inp + (size_t)b * CC * HWSZ + hw0;
    for (int idx = t; idx < 2048; idx += 256) {
        int c = idx >> 5, q = idx & 31;
        *reinterpret_cast<float4*>(&As[c * 132 + q * 4]) =
            *reinterpret_cast<const float4*>(ib + (size_t)c * HWSZ + q * 4);
    }
    for (int idx = t; idx < 1024; idx += 256) {
        int c = idx >> 4, q = idx & 15;
        *reinterpret_cast<float4*>(&Bs[c * 68 + q * 4]) =
            *reinterpret_cast<const float4*>(Wv + c * 64 + q * 4);
    }
    __syncthreads();

    int tc = t & 7, tp = t >> 3;     // co-oct (split 2 quads), px-quad (0..31)
    u64 acc[2][8];                    // [px-pair][co]
    {
        float4 b0 = *reinterpret_cast<const float4*>(bv + tc * 4);
        float4 b1 = *reinterpret_cast<const float4*>(bv + 32 + tc * 4);
        u64 bb[8] = {bcast2(b0.x), bcast2(b0.y), bcast2(b0.z), bcast2(b0.w),
                     bcast2(b1.x), bcast2(b1.y), bcast2(b1.z), bcast2(b1.w)};
#pragma unroll
        for (int pp = 0; pp < 2; pp++)
#pragma unroll
            for (int j = 0; j < 8; j++) acc[pp][j] = bb[j];
    }
#pragma unroll
    for (int k = 0; k < 64; k++) {
        float4 a4 = *reinterpret_cast<float4*>(&As[k * 132 + tp * 4]);
        u64 ap[2] = {pack2(a4.x, a4.y), pack2(a4.z, a4.w)};
        float4 w0 = *reinterpret_cast<float4*>(&Bs[k * 68 + tc * 4]);
        float4 w1 = *reinterpret_cast<float4*>(&Bs[k * 68 + 32 + tc * 4]);
        u64 wb[8] = {bcast2(w0.x), bcast2(w0.y), bcast2(w0.z), bcast2(w0.w),
                     bcast2(w1.x), bcast2(w1.y), bcast2(w1.z), bcast2(w1.w)};
#pragma unroll
        for (int pp = 0; pp < 2; pp++)
#pragma unroll
            for (int j = 0; j < 8; j++)
                fma2(acc[pp][j], ap[pp], wb[j], acc[pp][j]);
    }

    float* vb = g_value + (size_t)px0 * 64;
#pragma unroll
    for (int pp = 0; pp < 2; pp++) {
        float2 u[8];
#pragma unroll
        for (int j = 0; j < 8; j++) u[j] = unpk(acc[pp][j]);
        int pxe = tp * 4 + pp * 2;
        float4 e0 = {u[0].x, u[1].x, u[2].x, u[3].x};
        float4 e1 = {u[4].x, u[5].x, u[6].x, u[7].x};
        float4 o0 = {u[0].y, u[1].y, u[2].y, u[3].y};
        float4 o1 = {u[4].y, u[5].y, u[6].y, u[7].y};
        float* de = vb + pxe * 64;
        *reinterpret_cast<float4*>(de + tc * 4)      = e0;
        *reinterpret_cast<float4*>(de + 32 + tc * 4) = e1;
        *reinterpret_cast<float4*>(de + 64 + tc * 4) = o0;
        *reinterpret_cast<float4*>(de + 96 + tc * 4) = o1;
    }
}

// ---------------------------------------------------------------------------
// Kernel 2 (fully fused): depthwise 3x3 -> om GEMM -> deformable sampling ->
// output GEMM. 64 px of one row per block, om never leaves smem.
// smem (18544 floats = 74.2KB, 3 blocks/SM):
//   om_s  [0,6912)        overlays: itr (conv, [0,4288)), wo_s (phase C, [0,4352))
//   wom_s [6912,14080)    overlay:  wcell (phases A/B, 6656)
//   dwt   [14080,18432)   overlay:  sbT (phases B/C)
//   bom_s [18432,18544)
// ---------------------------------------------------------------------------
template<bool CHK>
__device__ __forceinline__ void gather_cells(const float* __restrict__ vb,
                                             const float* __restrict__ wc,
                                             int row, int xg, int c,
                                             float& ax, float& ay) {
    float ax1 = 0.f, ay1 = 0.f;
#pragma unroll
    for (int ry = 0; ry < 5; ry++) {
        int yy = row + ry - 2;
        if (CHK && (yy < 0 || yy >= HH)) continue;
        const float* rb = vb + (size_t)yy * WW * 64;
#pragma unroll
        for (int rx = 0; rx < 5; rx++) {
            int xx = xg + rx - 2;
            if (CHK && (xx < 0 || xx >= WW)) continue;
            float w = wc[ry * 5 + rx];
            float2 v = *reinterpret_cast<const float2*>(rb + xx * 64 + c);
            if (ry & 1) { ax1 += w * v.x; ay1 += w * v.y; }
            else        { ax  += w * v.x; ay  += w * v.y; }
        }
    }
    ax += ax1; ay += ay1;
}

__global__ void __launch_bounds__(256, 3) k_dwso(const float* __restrict__ inp,
                                                 const float* __restrict__ Wdw,
                                                 const float* __restrict__ bdw,
                                                 const float* __restrict__ Wom,
                                                 const float* __restrict__ bom,
                                                 const float* __restrict__ Wo,
                                                 float* __restrict__ out) {
    float* om_s  = dyn_smem;                 // 6912
    float* itr   = dyn_smem;                 // 4288 (conv only)
    float* wo_s  = dyn_smem;                 // 4352 (phase C only)
    float* wom_s = dyn_smem + 6912;          // 7168
    float* wcell = dyn_smem + 6912;          // 6656 (phases A/B)
    float* dwt   = dyn_smem + 14080;         // 4352
    float* sbT   = dyn_smem + 14080;         // 4352 (phases B/C)
    float* bom_s = dyn_smem + 18432;         // 112
    __shared__ int flags_s[256];

    int blk  = blockIdx.x;
    int tile = blk % 6;
    int row  = (blk / 6) % HH;
    int b    = blk / (6 * HH);
    int x0   = tile * 64;
    int t    = threadIdx.x;
    bool interior = (row >= 2) && (row < HH - 2) && (tile >= 1) && (tile <= 4);

    for (int idx = t; idx < 1792; idx += 256) {
        int c = idx / 28, q = idx % 28;
        *reinterpret_cast<float4*>(&wom_s[c * 112 + q * 4]) =
            *reinterpret_cast<const float4*>(Wom + c * OMD + q * 4);
    }
    if (t < 112) bom_s[t] = bom[t];

    // ---- depthwise conv, halo streamed row by row through itr ----
    int c  = t & 63;
    int p0 = t >> 6;
    float wd[9];
#pragma unroll
    for (int j = 0; j < 9; j++) wd[j] = Wdw[c * 9 + j];
    float accv[16];
    {
        float bd = bdw[c];
#pragma unroll
        for (int i = 0; i < 16; i++) accv[i] = bd;
    }
    const float* ibs = inp + (size_t)b * CC * HWSZ;

    for (int r = 0; r < 3; r++) {
        int gy = row - 1 + r;
        __syncthreads();
        if (gy >= 0 && gy < HH) {
            const float* rbase = ibs + (size_t)gy * WW + x0 - 1;
            for (int i = t; i < 64 * 66; i += 256) {
                int ci = i / 66, xx = i - ci * 66;
                int gx = x0 - 1 + xx;
                float v = 0.f;
                if (gx >= 0 && gx < WW)
                    v = rbase[(size_t)ci * HWSZ + xx];
                itr[ci * 67 + xx] = v;
            }
        } else {
            for (int i = t; i < 64 * 66; i += 256) {
                int ci = i / 66, xx = i - ci * 66;
                itr[ci * 67 + xx] = 0.f;
            }
        }
        __syncthreads();
        const float* itc = itr + c * 67 + p0;
        float w0 = wd[r * 3], w1 = wd[r * 3 + 1], w2 = wd[r * 3 + 2];
#pragma unroll
        for (int i = 0; i < 16; i++) {
            const float* q = itc + i * 4;
            accv[i] += q[0] * w0 + q[1] * w1 + q[2] * w2;
        }
    }
#pragma unroll
    for (int i = 0; i < 16; i++) dwt[c * 68 + p0 + i * 4] = accv[i];
    __syncthreads();

    // ---- om GEMM -> om_s (in smem) ----
    {
        int jq = t & 31, tp = t >> 5;
        if (jq < 27) {
            u64 acc[4][4];
#pragma unroll
            for (int j = 0; j < 4; j++) {
                u64 bb = bcast2(bom_s[jq * 4 + j]);
#pragma unroll
                for (int pp = 0; pp < 4; pp++) acc[pp][j] = bb;
            }
#pragma unroll
            for (int k = 0; k < 64; k++) {
                float4 a0 = *reinterpret_cast<float4*>(&dwt[k * 68 + tp * 8]);
                float4 a1 = *reinterpret_cast<float4*>(&dwt[k * 68 + tp * 8 + 4]);
                u64 ap[4] = {pack2(a0.x, a0.y), pack2(a0.z, a0.w),
                             pack2(a1.x, a1.y), pack2(a1.z, a1.w)};
                float4 w4 = *reinterpret_cast<float4*>(&wom_s[k * 112 + jq * 4]);
                u64 wb[4] = {bcast2(w4.x), bcast2(w4.y), bcast2(w4.z), bcast2(w4.w)};
#pragma unroll
                for (int pp = 0; pp < 4; pp++)
#pragma unroll
                    for (int j = 0; j < 4; j++)
                        fma2(acc[pp][j], ap[pp], wb[j], acc[pp][j]);
            }
#pragma unroll
            for (int pp = 0; pp < 4; pp++) {
                float2 u0 = unpk(acc[pp][0]), u1 = unpk(acc[pp][1]);
                float2 u2 = unpk(acc[pp][2]), u3 = unpk(acc[pp][3]);
                float4 oe = {u0.x, u1.x, u2.x, u3.x};
                float4 oo = {u0.y, u1.y, u2.y, u3.y};
                int px = tp * 8 + pp * 2;
                *reinterpret_cast<float4*>(om_s + px * OMU + jq * 4)       = oe;
                *reinterpret_cast<float4*>(om_s + (px + 1) * OMU + jq * 4) = oo;
            }
        }
    }
    __syncthreads();

    // ---- Phase A: per-(px,g) 5x5 cell weights (wcell overlays wom_s) ----
    {
        int px = t >> 2, g = t & 3;
        const float* omp = om_s + px * 108 + g * 27;
        float* wc = wcell + t * 26;
#pragma unroll
        for (int i = 0; i < 25; i++) wc[i] = 0.f;
        int ovf = 0;
#pragma unroll
        for (int k = 0; k < 9; k++) {
            float dx = omp[2 * k];
            float dy = omp[2 * k + 1];
            float m  = omp[18 + k];
            float fx = (float)(k % 3 - 1) + dx;
            float fy = (float)(k / 3 - 1) + dy;
            float fxf = floorf(fx), fyf = floorf(fy);
            int rx = (int)fxf + 2, ry = (int)fyf + 2;
            if ((unsigned)rx <= 3u && (unsigned)ry <= 3u) {
                float wx1 = fx - fxf, wy1 = fy - fyf;
                float wx0 = 1.f - wx1;
                float wa = m * (1.f - wy1), wb = m * wy1;
                int base = ry * 5 + rx;
                wc[base]     += wa * wx0;
                wc[base + 1] += wa * wx1;
                wc[base + 5] += wb * wx0;
                wc[base + 6] += wb * wx1;
            } else ovf = 1;
        }
        flags_s[t] = ovf;
    }
    __syncthreads();

    // ---- Phase B: warp per pixel, coalesced cell gathers -> sbT ----
    {
        int lane = t & 31, wrp = t >> 5;
        int cch = lane * 2;
        int g = lane >> 3;
        const float* vb = g_value + (size_t)b * HWSZ * 64;
        for (int i = 0; i < 8; i++) {
            int p  = wrp * 8 + i;
            int xg = x0 + p;
            const float* wc = wcell + (p * 4 + g) * 26;
            float ax = 0.f, ay = 0.f;
            if (interior) gather_cells<false>(vb, wc, row, xg, cch, ax, ay);
            else          gather_cells<true >(vb, wc, row, xg, cch, ax, ay);

            if (flags_s[p * 4 + g]) {      // rare: point left the 5x5 window
                const float* gomp = om_s + p * 108 + g * 27;
                for (int k = 0; k < 9; k++) {
                    float dx = gomp[2 * k];
                    float dy = gomp[2 * k + 1];
                    float m  = gomp[18 + k];
                    float fx = (float)(k % 3 - 1) + dx;
                    float fy = (float)(k / 3 - 1) + dy;
                    float fxf = floorf(fx), fyf = floorf(fy);
                    int rx = (int)fxf + 2, ry = (int)fyf + 2;
                    if ((unsigned)rx <= 3u && (unsigned)ry <= 3u) continue;
                    float wx1 = fx - fxf, wy1 = fy - fyf;
                    int xi = xg + (int)fxf, yi = row + (int)fyf;
                    for (int dyy = 0; dyy < 2; dyy++) {
                        int yy = yi + dyy;
                        float wy = dyy ? wy1 : 1.f - wy1;
                        bool vy = (yy >= 0) && (yy < HH);
                        int yc = min(max(yy, 0), HH - 1);
                        for (int dxx = 0; dxx < 2; dxx++) {
                            int xx = xi + dxx;
                            float wx = dxx ? wx1 : 1.f - wx1;
                            bool vx = (xx >= 0) && (xx < WW);
                            int xc = min(max(xx, 0), WW - 1);
                            float wgt = (vx && vy) ? (m * wy * wx) : 0.f;
                            float2 v = *reinterpret_cast<const float2*>(
                                vb + ((size_t)yc * WW + xc) * 64 + cch);
                            ax += wgt * v.x;
                            ay += wgt * v.y;
                        }
                    }
                }
            }
            sbT[cch * 68 + p]       = ax;
            sbT[(cch + 1) * 68 + p] = ay;
        }
    }
    __syncthreads();

    // ---- load Wo into om_s region (om dead now) ----
    for (int idx = t; idx < 1024; idx += 256) {
        int cc = idx >> 4, q = idx & 15;
        *reinterpret_cast<float4*>(&wo_s[cc * 68 + q * 4]) =
            *reinterpret_cast<const float4*>(Wo + cc * 64 + q * 4);
    }
    __syncthreads();

    // ---- Phase C: 64px x 64co GEMM, f32x2 px-packed -> NCHW out ----
    {
        int tx = t & 15, ty = t >> 4;
        u64 acc[2][4];
#pragma unroll
        for (int pp = 0; pp < 2; pp++)
#pragma unroll
            for (int j = 0; j < 4; j++) acc[pp][j] = 0ull;
#pragma unroll
        for (int k = 0; k < 64; k++) {
            float4 a4 = *reinterpret_cast<float4*>(&sbT[k * 68 + ty * 4]);
            u64 a0 = pack2(a4.x, a4.y), a1 = pack2(a4.z, a4.w);
            float4 w4 = *reinterpret_cast<float4*>(&wo_s[k * 68 + tx * 4]);
            u64 wb[4] = {bcast2(w4.x), bcast2(w4.y), bcast2(w4.z), bcast2(w4.w)};
#pragma unroll
            for (int j = 0; j < 4; j++) {
                fma2(acc[0][j], a0, wb[j], acc[0][j]);
                fma2(acc[1][j], a1, wb[j], acc[1][j]);
            }
        }
        float* ob = out + (size_t)b * CC * HWSZ + (size_t)row * WW + x0;
#pragma unroll
        for (int j = 0; j < 4; j++) {
            float2 u0 = unpk(acc[0][j]), u1 = unpk(acc[1][j]);
            float4 o = {u0.x, u0.y, u1.x, u1.y};
            int co = tx * 4 + j;
            *reinterpret_cast<float4*>(ob + (size_t)co * HWSZ + ty * 4) = o;
        }
    }
}

// ---------------------------------------------------------------------------
extern "C" void kernel_launch(void* const* d_in, const int* in_sizes, int n_in,
                              void* d_out, int out_size) {
    const float* inp = (const float*)d_in[0];
    const float* Wv  = (const float*)d_in[1];
    const float* bv  = (const float*)d_in[2];
    const float* Wdw = (const float*)d_in[3];
    const float* bdw = (const float*)d_in[4];
    const float* Wom = (const float*)d_in[5];
    const float* bom = (const float*)d_in[6];
    const float* Wo  = (const float*)d_in[7];
    float* out = (float*)d_out;

    const int VAL_SMEM  = (64 * 132 + 64 * 68) * 4;
    const int DWSO_SMEM = 18544 * 4;
    static int smem_set = 0;
    if (!smem_set) {
        cudaFuncSetAttribute(k_value, cudaFuncAttributeMaxDynamicSharedMemorySize, VAL_SMEM);
        cudaFuncSetAttribute(k_dwso,  cudaFuncAttributeMaxDynamicSharedMemorySize, DWSO_SMEM);
        smem_set = 1;
    }

    k_value<<<NPIX / 128,  256, VAL_SMEM>>>  (inp, Wv, bv);
    k_dwso <<<BB * HH * 6, 256, DWSO_SMEM>>> (inp, Wdw, bdw, Wom, bom, Wo, out);
}